// round 4
// baseline (speedup 1.0000x reference)
#include <cuda_runtime.h>
#include <math.h>

constexpr int L   = 31744;   // 31*32*32 tokens
constexpr int NCH = 248;     // scan chunks
constexpr int LC  = 128;     // chunk length

// ----------------------------- scratch layout ------------------------------
constexpr size_t O_XN    = 0;
constexpr size_t O_XI    = O_XN    + (size_t)L * 64;
constexpr size_t O_Z     = O_XI    + (size_t)L * 128;
constexpr size_t O_XC    = O_Z     + (size_t)L * 128;
constexpr size_t O_DELTA = O_XC    + (size_t)L * 128;
constexpr size_t O_B     = O_DELTA + (size_t)L * 128;
constexpr size_t O_C     = O_B     + (size_t)L * 16;
constexpr size_t O_YM    = O_C     + (size_t)L * 16;
constexpr size_t O_RES1  = O_YM    + (size_t)L * 128;
constexpr size_t O_XN2   = O_RES1  + (size_t)L * 64;
constexpr size_t O_HMID  = O_XN2   + (size_t)L * 64;
constexpr size_t O_HLOC  = O_HMID  + (size_t)L * 128;
constexpr size_t O_P     = O_HLOC  + (size_t)NCH * 2048;
constexpr size_t O_HIN   = O_P     + (size_t)NCH * 2048;
constexpr size_t O_WCOMB = O_HIN   + (size_t)NCH * 2048;
constexpr size_t TOTALF  = O_WCOMB + 128 * 160;

__device__ float g_buf[TOTALF];

__device__ __forceinline__ float softplusf(float x) {
    return (x > 20.f) ? x : log1pf(__expf(x));
}

// Wcomb[c][0:128] = Wx[c,0:4]@Wdt ; [128:144]=B cols ; [144:160]=C cols
__global__ void prep_kernel(const float* __restrict__ Wx,
                            const float* __restrict__ Wdt) {
    int idx = blockIdx.x * blockDim.x + threadIdx.x;
    if (idx >= 128 * 160) return;
    int c = idx / 160, j = idx - c * 160;
    float v;
    if (j < 128) {
        v = 0.f;
        #pragma unroll
        for (int r = 0; r < 4; r++) v = fmaf(Wx[c * 36 + r], Wdt[r * 128 + j], v);
    } else if (j < 144) v = Wx[c * 36 + 4 + (j - 128)];
    else                v = Wx[c * 36 + 20 + (j - 144)];
    g_buf[O_WCOMB + (size_t)c * 160 + j] = v;
}

// LayerNorm over 64 channels. SRC=0: in is [C,L]; SRC=1: in is [L,64]. out [L,64].
template <int SRC>
__global__ void __launch_bounds__(256) ln_kernel(const float* __restrict__ in,
                                                 const float* __restrict__ w,
                                                 const float* __restrict__ b,
                                                 float* __restrict__ out) {
    int l = blockIdx.x * 256 + threadIdx.x;
    float v[64];
    float mu = 0.f;
    if (SRC == 0) {
        #pragma unroll
        for (int c = 0; c < 64; c++) { v[c] = in[(size_t)c * L + l]; mu += v[c]; }
    } else {
        #pragma unroll
        for (int q = 0; q < 16; q++) {
            float4 t = *(const float4*)&in[(size_t)l * 64 + q * 4];
            v[q*4+0]=t.x; v[q*4+1]=t.y; v[q*4+2]=t.z; v[q*4+3]=t.w;
            mu += t.x + t.y + t.z + t.w;
        }
    }
    mu *= (1.f / 64.f);
    float var = 0.f;
    #pragma unroll
    for (int c = 0; c < 64; c++) { float d = v[c] - mu; var = fmaf(d, d, var); }
    float rs = rsqrtf(var * (1.f / 64.f) + 1e-5f);
    #pragma unroll
    for (int q = 0; q < 16; q++) {
        float4 o;
        o.x = (v[q*4+0]-mu)*rs*w[q*4+0]+b[q*4+0];
        o.y = (v[q*4+1]-mu)*rs*w[q*4+1]+b[q*4+1];
        o.z = (v[q*4+2]-mu)*rs*w[q*4+2]+b[q*4+2];
        o.w = (v[q*4+3]-mu)*rs*w[q*4+3]+b[q*4+3];
        *(float4*)&out[(size_t)l * 64 + q * 4] = o;
    }
}

// causal depthwise conv k=4 + relu : xi [L,128] -> xc [L,128]
__global__ void __launch_bounds__(256) conv_kernel(const float* __restrict__ xi,
                                                   const float* __restrict__ cw,
                                                   float* __restrict__ xc) {
    int idx = blockIdx.x * 256 + threadIdx.x;  // l*128 + d
    int d = idx & 127, l = idx >> 7;
    float4 w = *(const float4*)&cw[d * 4];
    float acc = w.w * xi[idx];
    if (l > 0) acc = fmaf(w.z, xi[idx - 128], acc);
    if (l > 1) acc = fmaf(w.y, xi[idx - 256], acc);
    if (l > 2) acc = fmaf(w.x, xi[idx - 384], acc);
    xc[idx] = fmaxf(acc, 0.f);
}

// -------- generic skinny GEMM Y[L,N] = X[L,K] @ W[K,N], fused epilogue -----
// MODE 1: split -> O0 xi (cols<128) / O1 z (cols>=128)
// MODE 2: cols<128 -> O0 delta=softplus(acc+E0[col]); 128..143 -> O1 B; 144.. -> O2 C
// MODE 3: O0 res1[l,c] = acc + E0[c*L+l]   (E0 = input x, [C,L])
// MODE 4: gated FFN: g=cols col0..+3, v=128+col0..+3 ; O0 = silu(g)*v  [L,128]
// MODE 5: O0[c*L+l] = E0[l*64+c] + acc      (output transpose + residual)
template <int K, int N, int TT, int TJ, int MODE, int NT>
__global__ void __launch_bounds__(NT) gemm_k(const float* __restrict__ X,
                                             const float* __restrict__ W,
                                             float* __restrict__ O0,
                                             float* __restrict__ O1,
                                             float* __restrict__ O2,
                                             const float* __restrict__ E0) {
    constexpr int BM  = 64;
    constexpr int JQ  = N / TJ;
    constexpr int STR = BM + 4;
    __shared__ float Xs[K * STR];

    const int tid = threadIdx.x;
    const int l0  = blockIdx.x * BM;

    for (int idx = tid; idx < BM * K; idx += NT) {
        int t = idx / K, c = idx - t * K;
        Xs[c * STR + t] = X[(size_t)(l0 + t) * K + c];
    }
    __syncthreads();

    const int jq   = tid % JQ;
    const int tq   = tid / JQ;
    const int t0   = tq * TT;
    const int col0 = (MODE == 4) ? jq * 4 : jq * TJ;

    float acc[TT][TJ];
    #pragma unroll
    for (int t = 0; t < TT; t++)
        #pragma unroll
        for (int j = 0; j < TJ; j++) acc[t][j] = 0.f;

    #pragma unroll 4
    for (int c = 0; c < K; c++) {
        float xv[TT];
        #pragma unroll
        for (int q = 0; q < TT / 4; q++) {
            float4 x4 = *(const float4*)&Xs[c * STR + t0 + q * 4];
            xv[q*4+0]=x4.x; xv[q*4+1]=x4.y; xv[q*4+2]=x4.z; xv[q*4+3]=x4.w;
        }
        float wv[TJ];
        if (MODE == 4) {
            float4 a = *(const float4*)&W[(size_t)c * N + col0];
            float4 bq = *(const float4*)&W[(size_t)c * N + 128 + col0];
            wv[0]=a.x; wv[1]=a.y; wv[2]=a.z; wv[3]=a.w;
            wv[4]=bq.x; wv[5]=bq.y; wv[6]=bq.z; wv[7]=bq.w;
        } else {
            #pragma unroll
            for (int q = 0; q < TJ / 4; q++) {
                float4 a = *(const float4*)&W[(size_t)c * N + col0 + q * 4];
                wv[q*4+0]=a.x; wv[q*4+1]=a.y; wv[q*4+2]=a.z; wv[q*4+3]=a.w;
            }
        }
        #pragma unroll
        for (int t = 0; t < TT; t++)
            #pragma unroll
            for (int j = 0; j < TJ; j++)
                acc[t][j] = fmaf(xv[t], wv[j], acc[t][j]);
    }

    #pragma unroll
    for (int t = 0; t < TT; t++) {
        const int l = l0 + t0 + t;
        if (MODE == 1) {
            float* dst = (col0 < 128) ? (O0 + (size_t)l * 128 + col0)
                                      : (O1 + (size_t)l * 128 + (col0 - 128));
            *(float4*)dst       = make_float4(acc[t][0], acc[t][1], acc[t][2], acc[t][3]);
            *(float4*)(dst + 4) = make_float4(acc[t][4], acc[t][5], acc[t][6], acc[t][7]);
        } else if (MODE == 2) {
            if (col0 < 128) {
                #pragma unroll
                for (int j = 0; j < TJ; j++)
                    O0[(size_t)l * 128 + col0 + j] = softplusf(acc[t][j] + E0[col0 + j]);
            } else if (col0 < 144) {
                #pragma unroll
                for (int j = 0; j < TJ; j++)
                    O1[(size_t)l * 16 + (col0 - 128) + j] = acc[t][j];
            } else {
                #pragma unroll
                for (int j = 0; j < TJ; j++)
                    O2[(size_t)l * 16 + (col0 - 144) + j] = acc[t][j];
            }
        } else if (MODE == 3) {
            #pragma unroll
            for (int j = 0; j < TJ; j++)
                O0[(size_t)l * 64 + col0 + j] = acc[t][j] + E0[(size_t)(col0 + j) * L + l];
        } else if (MODE == 4) {
            #pragma unroll
            for (int j = 0; j < 4; j++) {
                float g = acc[t][j], vv = acc[t][j + 4];
                float s = 1.f / (1.f + __expf(-g));
                O0[(size_t)l * 128 + col0 + j] = g * s * vv;
            }
        } else {  // MODE 5
            #pragma unroll
            for (int j = 0; j < TJ; j++)
                O0[(size_t)(col0 + j) * L + l] = E0[(size_t)l * 64 + col0 + j] + acc[t][j];
        }
    }
}

// ------------------- selective scan: phase A (local scans) -----------------
__global__ void __launch_bounds__(256) scan_a(const float* __restrict__ u,
                                              const float* __restrict__ dl,
                                              const float* __restrict__ Bm,
                                              const float* __restrict__ Alog) {
    __shared__ float Bs[LC * 16];
    const int tid = threadIdx.x, chunk = blockIdx.x, l0 = chunk * LC;
    for (int i = tid; i < LC * 16; i += 256) Bs[i] = Bm[(size_t)l0 * 16 + i];
    __syncthreads();
    const int d = tid >> 1, s0 = (tid & 1) * 8;
    float A[8], h[8], sd = 0.f;
    #pragma unroll
    for (int j = 0; j < 8; j++) { A[j] = -__expf(Alog[d * 16 + s0 + j]); h[j] = 0.f; }
    for (int l = 0; l < LC; l++) {
        float del = dl[(size_t)(l0 + l) * 128 + d];
        float du  = del * u[(size_t)(l0 + l) * 128 + d];
        sd += del;
        #pragma unroll
        for (int j = 0; j < 8; j++)
            h[j] = __expf(del * A[j]) * h[j] + du * Bs[l * 16 + s0 + j];
    }
    size_t base = (size_t)chunk * 2048 + d * 16 + s0;
    #pragma unroll
    for (int j = 0; j < 8; j++) {
        g_buf[O_HLOC + base + j] = h[j];
        g_buf[O_P + base + j]    = __expf(sd * A[j]);  // exact product of per-step decays
    }
}

// ----- phase B: per-(d,s) lane, Hillis-Steele scan over 248 chunk maps -----
__global__ void __launch_bounds__(256) scan_b() {
    __shared__ float a0[256], b0[256], a1[256], b1[256];
    const int lane = blockIdx.x;      // 0..2047
    const int c = threadIdx.x;
    float a = 1.f, b = 0.f;
    if (c < NCH) {
        a = g_buf[O_P + (size_t)c * 2048 + lane];
        b = g_buf[O_HLOC + (size_t)c * 2048 + lane];
    }
    a0[c] = a; b0[c] = b;
    __syncthreads();
    bool pp = true;  // true -> current values in buf0
    #pragma unroll
    for (int d = 1; d < 256; d <<= 1) {
        float na = a, nb = b;
        if (c >= d) {
            float la = pp ? a0[c - d] : a1[c - d];
            float lb = pp ? b0[c - d] : b1[c - d];
            na = la * a;
            nb = a * lb + b;
        }
        __syncthreads();
        a = na; b = nb;
        if (pp) { a1[c] = a; b1[c] = b; } else { a0[c] = a; b0[c] = b; }
        pp = !pp;
        __syncthreads();
    }
    if (c < NCH) {
        float hin = (c == 0) ? 0.f : (pp ? b0[c - 1] : b1[c - 1]);
        g_buf[O_HIN + (size_t)c * 2048 + lane] = hin;
    }
}

// -------- phase C: replay with carry-in, y = (C.h + u*D) * silu(z) ---------
__global__ void __launch_bounds__(256) scan_c(const float* __restrict__ u,
                                              const float* __restrict__ dl,
                                              const float* __restrict__ Bm,
                                              const float* __restrict__ Cm,
                                              const float* __restrict__ Alog,
                                              const float* __restrict__ Dp,
                                              const float* __restrict__ z,
                                              float* __restrict__ ym) {
    __shared__ float Bs[LC * 16], Cs[LC * 16];
    const int tid = threadIdx.x, chunk = blockIdx.x, l0 = chunk * LC;
    for (int i = tid; i < LC * 16; i += 256) {
        Bs[i] = Bm[(size_t)l0 * 16 + i];
        Cs[i] = Cm[(size_t)l0 * 16 + i];
    }
    __syncthreads();
    const int d = tid >> 1, s0 = (tid & 1) * 8;
    float A[8], h[8];
    const float Dd = Dp[d];
    size_t base = (size_t)chunk * 2048 + d * 16 + s0;
    #pragma unroll
    for (int j = 0; j < 8; j++) {
        A[j] = -__expf(Alog[d * 16 + s0 + j]);
        h[j] = g_buf[O_HIN + base + j];
    }
    for (int l = 0; l < LC; l++) {
        float del = dl[(size_t)(l0 + l) * 128 + d];
        float ul  = u[(size_t)(l0 + l) * 128 + d];
        float du  = del * ul;
        float part = 0.f;
        #pragma unroll
        for (int j = 0; j < 8; j++) {
            h[j] = __expf(del * A[j]) * h[j] + du * Bs[l * 16 + s0 + j];
            part = fmaf(h[j], Cs[l * 16 + s0 + j], part);
        }
        float other = __shfl_xor_sync(0xffffffffu, part, 1);
        float y = part + other + ul * Dd;
        if ((tid & 1) == 0) {
            float zz = z[(size_t)(l0 + l) * 128 + d];
            ym[(size_t)(l0 + l) * 128 + d] = y * zz / (1.f + __expf(-zz));
        }
    }
}

// ---------------------------------------------------------------------------
extern "C" void kernel_launch(void* const* d_in, const int* in_sizes, int n_in,
                              void* d_out, int out_size) {
    const float* x      = (const float*)d_in[0];
    const float* ln1_w  = (const float*)d_in[1];
    const float* ln1_b  = (const float*)d_in[2];
    const float* W_in   = (const float*)d_in[3];
    const float* conv_w = (const float*)d_in[4];
    const float* W_xp   = (const float*)d_in[5];
    const float* W_dt   = (const float*)d_in[6];
    const float* dt_b   = (const float*)d_in[7];
    const float* A_log  = (const float*)d_in[8];
    const float* D_ssm  = (const float*)d_in[9];
    const float* W_out  = (const float*)d_in[10];
    const float* ln2_w  = (const float*)d_in[11];
    const float* ln2_b  = (const float*)d_in[12];
    const float* W_f1   = (const float*)d_in[13];
    const float* W_f2   = (const float*)d_in[14];
    float* out = (float*)d_out;

    float* gb = nullptr;
    cudaGetSymbolAddress((void**)&gb, g_buf);

    prep_kernel<<<80, 256>>>(W_xp, W_dt);
    ln_kernel<0><<<L / 256, 256>>>(x, ln1_w, ln1_b, gb + O_XN);
    gemm_k<64, 256, 8, 8, 1, 256><<<L / 64, 256>>>(gb + O_XN, W_in,
        gb + O_XI, gb + O_Z, nullptr, nullptr);
    conv_kernel<<<(L * 128) / 256, 256>>>(gb + O_XI, conv_w, gb + O_XC);
    gemm_k<128, 160, 8, 8, 2, 160><<<L / 64, 160>>>(gb + O_XC, gb + O_WCOMB,
        gb + O_DELTA, gb + O_B, gb + O_C, dt_b);
    scan_a<<<NCH, 256>>>(gb + O_XC, gb + O_DELTA, gb + O_B, A_log);
    scan_b<<<2048, 256>>>();
    scan_c<<<NCH, 256>>>(gb + O_XC, gb + O_DELTA, gb + O_B, gb + O_C,
                         A_log, D_ssm, gb + O_Z, gb + O_YM);
    gemm_k<128, 64, 8, 4, 3, 128><<<L / 64, 128>>>(gb + O_YM, W_out,
        gb + O_RES1, nullptr, nullptr, x);
    ln_kernel<1><<<L / 256, 256>>>(gb + O_RES1, ln2_w, ln2_b, gb + O_XN2);
    gemm_k<64, 256, 8, 8, 4, 256><<<L / 64, 256>>>(gb + O_XN2, W_f1,
        gb + O_HMID, nullptr, nullptr, nullptr);
    gemm_k<128, 64, 8, 4, 5, 128><<<L / 64, 128>>>(gb + O_HMID, W_f2,
        out, nullptr, nullptr, gb + O_RES1);
}

// round 6
// speedup vs baseline: 1.0261x; 1.0261x over previous
#include <cuda_runtime.h>
#include <math.h>

constexpr int L   = 31744;   // 31*32*32 tokens
constexpr int NCH = 248;     // scan chunks
constexpr int LC  = 128;     // chunk length

// ----------------------------- scratch layout ------------------------------
constexpr size_t O_XI    = 0;
constexpr size_t O_Z     = O_XI    + (size_t)L * 128;
constexpr size_t O_XC    = O_Z     + (size_t)L * 128;
constexpr size_t O_DELTA = O_XC    + (size_t)L * 128;
constexpr size_t O_B     = O_DELTA + (size_t)L * 128;
constexpr size_t O_C     = O_B     + (size_t)L * 16;
constexpr size_t O_YM    = O_C     + (size_t)L * 16;
constexpr size_t O_RES1  = O_YM    + (size_t)L * 128;
constexpr size_t O_HMID  = O_RES1  + (size_t)L * 64;
constexpr size_t O_HLOC  = O_HMID  + (size_t)L * 128;
constexpr size_t O_P     = O_HLOC  + (size_t)NCH * 2048;
constexpr size_t O_HIN   = O_P     + (size_t)NCH * 2048;
constexpr size_t O_WCOMB = O_HIN   + (size_t)NCH * 2048;
constexpr size_t TOTALF  = O_WCOMB + 128 * 160;

__device__ float g_buf[TOTALF];

__device__ __forceinline__ float softplusf(float x) {
    return (x > 20.f) ? x : log1pf(__expf(x));
}

// Wcomb[c][0:128] = Wx[c,0:4]@Wdt ; [128:144]=B cols ; [144:160]=C cols
__global__ void prep_kernel(const float* __restrict__ Wx,
                            const float* __restrict__ Wdt) {
    int idx = blockIdx.x * blockDim.x + threadIdx.x;
    if (idx >= 128 * 160) return;
    int c = idx / 160, j = idx - c * 160;
    float v;
    if (j < 128) {
        v = 0.f;
        #pragma unroll
        for (int r = 0; r < 4; r++) v = fmaf(Wx[c * 36 + r], Wdt[r * 128 + j], v);
    } else if (j < 144) v = Wx[c * 36 + 4 + (j - 128)];
    else                v = Wx[c * 36 + 20 + (j - 144)];
    g_buf[O_WCOMB + (size_t)c * 160 + j] = v;
}

// causal depthwise conv k=4 + relu, float4 over channels
__global__ void __launch_bounds__(256) conv_kernel(const float* __restrict__ xi,
                                                   const float* __restrict__ cw,
                                                   float* __restrict__ xc) {
    int idx = blockIdx.x * 256 + threadIdx.x;    // over L*32
    int q = idx & 31, l = idx >> 5;
    int d0 = q * 4;
    const float4* xr = (const float4*)xi;
    float4 zero = make_float4(0.f, 0.f, 0.f, 0.f);
    float4 x0 = xr[(size_t)l * 32 + q];
    float4 x1 = (l > 0) ? xr[(size_t)(l - 1) * 32 + q] : zero;
    float4 x2 = (l > 1) ? xr[(size_t)(l - 2) * 32 + q] : zero;
    float4 x3 = (l > 2) ? xr[(size_t)(l - 3) * 32 + q] : zero;
    float4 w0 = *(const float4*)&cw[(d0 + 0) * 4];
    float4 w1 = *(const float4*)&cw[(d0 + 1) * 4];
    float4 w2 = *(const float4*)&cw[(d0 + 2) * 4];
    float4 w3 = *(const float4*)&cw[(d0 + 3) * 4];
    float4 o;
    o.x = fmaxf(fmaf(w0.w, x0.x, fmaf(w0.z, x1.x, fmaf(w0.y, x2.x, w0.x * x3.x))), 0.f);
    o.y = fmaxf(fmaf(w1.w, x0.y, fmaf(w1.z, x1.y, fmaf(w1.y, x2.y, w1.x * x3.y))), 0.f);
    o.z = fmaxf(fmaf(w2.w, x0.z, fmaf(w2.z, x1.z, fmaf(w2.y, x2.z, w2.x * x3.z))), 0.f);
    o.w = fmaxf(fmaf(w3.w, x0.w, fmaf(w3.z, x1.w, fmaf(w3.y, x2.w, w3.x * x3.w))), 0.f);
    ((float4*)xc)[(size_t)l * 32 + q] = o;
}

// -------- skinny GEMM Y[L,N] = X[L,K] @ W[K,N], W staged in smem chunks ----
// MODE 1: split -> O0 xi (cols<128) / O1 z (cols>=128)
// MODE 2: cols<128 -> O0 delta=softplus(acc+E0[col]); 128..143 -> O1 B; 144.. -> O2 C
// MODE 3: O0 res1[l,c] = acc + E0[c*L+l]   (E0 = input x, [C,L])
// MODE 4: gated FFN: g=cols col0..+3, v=128+col0..+3 ; O0 = silu(g)*v  [L,128]
// MODE 5: O0[c*L+l] = E0[l*64+c] + acc      (output transpose + residual)
// LNSRC 0: none. 1: X is original x [C,L], apply LN(w,b) in the tile (K==64).
//          2: X is [L,64] row-major, apply LN in the tile (K==64).
template <int K, int N, int TT, int TJ, int MODE, int NT, int LNSRC>
__global__ void __launch_bounds__(NT) gemm_k(const float* __restrict__ X,
                                             const float* __restrict__ W,
                                             float* __restrict__ O0,
                                             float* __restrict__ O1,
                                             float* __restrict__ O2,
                                             const float* __restrict__ E0,
                                             const float* __restrict__ lnw,
                                             const float* __restrict__ lnb) {
    constexpr int BM  = 64;
    constexpr int JQ  = N / TJ;
    constexpr int STR = BM + 4;
    constexpr int KC  = 16;
    __shared__ float Xs[K * STR];
    __shared__ float Ws[KC * N];

    const int tid = threadIdx.x;
    const int l0  = blockIdx.x * BM;

    // ---- stage X ----
    if (LNSRC == 1) {
        for (int idx = tid; idx < K * BM; idx += NT) {
            int c = idx / BM, t = idx - c * BM;
            Xs[c * STR + t] = X[(size_t)c * L + l0 + t];
        }
    } else {
        for (int idx = tid; idx < BM * K; idx += NT) {
            int t = idx / K, c = idx - t * K;
            Xs[c * STR + t] = X[(size_t)(l0 + t) * K + c];
        }
    }
    __syncthreads();

    if (LNSRC != 0) {
        if (tid < BM) {
            float mu = 0.f, sq = 0.f;
            #pragma unroll
            for (int c = 0; c < K; c++) {
                float v = Xs[c * STR + tid];
                mu += v; sq = fmaf(v, v, sq);
            }
            mu *= (1.f / K);
            float var = sq * (1.f / K) - mu * mu;
            float rs = rsqrtf(var + 1e-5f);
            #pragma unroll
            for (int c = 0; c < K; c++)
                Xs[c * STR + tid] = (Xs[c * STR + tid] - mu) * rs * lnw[c] + lnb[c];
        }
        __syncthreads();
    }

    const int jq   = tid % JQ;
    const int tq   = tid / JQ;
    const int t0   = tq * TT;
    const int col0 = (MODE == 4) ? jq * 4 : jq * TJ;

    float acc[TT][TJ];
    #pragma unroll
    for (int t = 0; t < TT; t++)
        #pragma unroll
        for (int j = 0; j < TJ; j++) acc[t][j] = 0.f;

    for (int kc = 0; kc < K; kc += KC) {
        // stage W chunk (contiguous)
        for (int idx = tid * 4; idx < KC * N; idx += NT * 4)
            *(float4*)&Ws[idx] = *(const float4*)&W[(size_t)kc * N + idx];
        __syncthreads();

        #pragma unroll
        for (int cc = 0; cc < KC; cc++) {
            const int c = kc + cc;
            float xv[TT];
            #pragma unroll
            for (int q = 0; q < TT / 4; q++) {
                float4 x4 = *(const float4*)&Xs[c * STR + t0 + q * 4];
                xv[q*4+0]=x4.x; xv[q*4+1]=x4.y; xv[q*4+2]=x4.z; xv[q*4+3]=x4.w;
            }
            float wv[TJ];
            if (MODE == 4) {
                float4 a  = *(const float4*)&Ws[cc * N + col0];
                float4 bq = *(const float4*)&Ws[cc * N + 128 + col0];
                wv[0]=a.x; wv[1]=a.y; wv[2]=a.z; wv[3]=a.w;
                wv[4]=bq.x; wv[5]=bq.y; wv[6]=bq.z; wv[7]=bq.w;
            } else {
                #pragma unroll
                for (int q = 0; q < TJ / 4; q++) {
                    float4 a = *(const float4*)&Ws[cc * N + col0 + q * 4];
                    wv[q*4+0]=a.x; wv[q*4+1]=a.y; wv[q*4+2]=a.z; wv[q*4+3]=a.w;
                }
            }
            #pragma unroll
            for (int t = 0; t < TT; t++)
                #pragma unroll
                for (int j = 0; j < TJ; j++)
                    acc[t][j] = fmaf(xv[t], wv[j], acc[t][j]);
        }
        __syncthreads();
    }

    #pragma unroll
    for (int t = 0; t < TT; t++) {
        const int l = l0 + t0 + t;
        if (MODE == 1) {
            float* dst = (col0 < 128) ? (O0 + (size_t)l * 128 + col0)
                                      : (O1 + (size_t)l * 128 + (col0 - 128));
            *(float4*)dst       = make_float4(acc[t][0], acc[t][1], acc[t][2], acc[t][3]);
            *(float4*)(dst + 4) = make_float4(acc[t][4], acc[t][5], acc[t][6], acc[t][7]);
        } else if (MODE == 2) {
            if (col0 < 128) {
                #pragma unroll
                for (int j = 0; j < TJ; j++)
                    O0[(size_t)l * 128 + col0 + j] = softplusf(acc[t][j] + E0[col0 + j]);
            } else if (col0 < 144) {
                #pragma unroll
                for (int j = 0; j < TJ; j++)
                    O1[(size_t)l * 16 + (col0 - 128) + j] = acc[t][j];
            } else {
                #pragma unroll
                for (int j = 0; j < TJ; j++)
                    O2[(size_t)l * 16 + (col0 - 144) + j] = acc[t][j];
            }
        } else if (MODE == 3) {
            #pragma unroll
            for (int j = 0; j < TJ; j++)
                O0[(size_t)l * 64 + col0 + j] = acc[t][j] + E0[(size_t)(col0 + j) * L + l];
        } else if (MODE == 4) {
            #pragma unroll
            for (int j = 0; j < 4; j++) {
                float g = acc[t][j], vv = acc[t][j + 4];
                float s = 1.f / (1.f + __expf(-g));
                O0[(size_t)l * 128 + col0 + j] = g * s * vv;
            }
        } else {  // MODE 5
            #pragma unroll
            for (int j = 0; j < TJ; j++)
                O0[(size_t)(col0 + j) * L + l] = E0[(size_t)l * 64 + col0 + j] + acc[t][j];
        }
    }
}

// ------------------- selective scan: phase A (local scans) -----------------
__global__ void __launch_bounds__(256) scan_a(const float* __restrict__ u,
                                              const float* __restrict__ dl,
                                              const float* __restrict__ Bm,
                                              const float* __restrict__ Alog) {
    __shared__ float Bs[LC * 16];
    const int tid = threadIdx.x, chunk = blockIdx.x, l0 = chunk * LC;
    for (int i = tid; i < LC * 16; i += 256) Bs[i] = Bm[(size_t)l0 * 16 + i];
    __syncthreads();
    const int d = tid >> 1, s0 = (tid & 1) * 8;
    float A[8], h[8], sd = 0.f;
    #pragma unroll
    for (int j = 0; j < 8; j++) { A[j] = -__expf(Alog[d * 16 + s0 + j]); h[j] = 0.f; }
    for (int l = 0; l < LC; l++) {
        float del = dl[(size_t)(l0 + l) * 128 + d];
        float du  = del * u[(size_t)(l0 + l) * 128 + d];
        sd += del;
        #pragma unroll
        for (int j = 0; j < 8; j++)
            h[j] = __expf(del * A[j]) * h[j] + du * Bs[l * 16 + s0 + j];
    }
    size_t base = (size_t)chunk * 2048 + d * 16 + s0;
    #pragma unroll
    for (int j = 0; j < 8; j++) {
        g_buf[O_HLOC + base + j] = h[j];
        g_buf[O_P + base + j]    = __expf(sd * A[j]);
    }
}

// ----- phase B: per-(d,s) lane, Hillis-Steele scan over 248 chunk maps -----
__global__ void __launch_bounds__(256) scan_b() {
    __shared__ float a0[256], b0[256], a1[256], b1[256];
    const int lane = blockIdx.x;      // 0..2047
    const int c = threadIdx.x;
    float a = 1.f, b = 0.f;
    if (c < NCH) {
        a = g_buf[O_P + (size_t)c * 2048 + lane];
        b = g_buf[O_HLOC + (size_t)c * 2048 + lane];
    }
    a0[c] = a; b0[c] = b;
    __syncthreads();
    bool pp = true;
    #pragma unroll
    for (int d = 1; d < 256; d <<= 1) {
        float na = a, nb = b;
        if (c >= d) {
            float la = pp ? a0[c - d] : a1[c - d];
            float lb = pp ? b0[c - d] : b1[c - d];
            na = la * a;
            nb = a * lb + b;
        }
        __syncthreads();
        a = na; b = nb;
        if (pp) { a1[c] = a; b1[c] = b; } else { a0[c] = a; b0[c] = b; }
        pp = !pp;
        __syncthreads();
    }
    if (c < NCH) {
        float hin = (c == 0) ? 0.f : (pp ? b0[c - 1] : b1[c - 1]);
        g_buf[O_HIN + (size_t)c * 2048 + lane] = hin;
    }
}

// -------- phase C: replay with carry-in, y = (C.h + u*D) * silu(z) ---------
__global__ void __launch_bounds__(256) scan_c(const float* __restrict__ u,
                                              const float* __restrict__ dl,
                                              const float* __restrict__ Bm,
                                              const float* __restrict__ Cm,
                                              const float* __restrict__ Alog,
                                              const float* __restrict__ Dp,
                                              const float* __restrict__ z,
                                              float* __restrict__ ym) {
    __shared__ float Bs[LC * 16], Cs[LC * 16];
    const int tid = threadIdx.x, chunk = blockIdx.x, l0 = chunk * LC;
    for (int i = tid; i < LC * 16; i += 256) {
        Bs[i] = Bm[(size_t)l0 * 16 + i];
        Cs[i] = Cm[(size_t)l0 * 16 + i];
    }
    __syncthreads();
    const int d = tid >> 1, s0 = (tid & 1) * 8;
    float A[8], h[8];
    const float Dd = Dp[d];
    size_t base = (size_t)chunk * 2048 + d * 16 + s0;
    #pragma unroll
    for (int j = 0; j < 8; j++) {
        A[j] = -__expf(Alog[d * 16 + s0 + j]);
        h[j] = g_buf[O_HIN + base + j];
    }
    for (int l = 0; l < LC; l++) {
        float del = dl[(size_t)(l0 + l) * 128 + d];
        float ul  = u[(size_t)(l0 + l) * 128 + d];
        float du  = del * ul;
        float part = 0.f;
        #pragma unroll
        for (int j = 0; j < 8; j++) {
            h[j] = __expf(del * A[j]) * h[j] + du * Bs[l * 16 + s0 + j];
            part = fmaf(h[j], Cs[l * 16 + s0 + j], part);
        }
        float other = __shfl_xor_sync(0xffffffffu, part, 1);
        float y = part + other + ul * Dd;
        if ((tid & 1) == 0) {
            float zz = z[(size_t)(l0 + l) * 128 + d];
            ym[(size_t)(l0 + l) * 128 + d] = y * zz / (1.f + __expf(-zz));
        }
    }
}

// ---------------------------------------------------------------------------
extern "C" void kernel_launch(void* const* d_in, const int* in_sizes, int n_in,
                              void* d_out, int out_size) {
    const float* x      = (const float*)d_in[0];
    const float* ln1_w  = (const float*)d_in[1];
    const float* ln1_b  = (const float*)d_in[2];
    const float* W_in   = (const float*)d_in[3];
    const float* conv_w = (const float*)d_in[4];
    const float* W_xp   = (const float*)d_in[5];
    const float* W_dt   = (const float*)d_in[6];
    const float* dt_b   = (const float*)d_in[7];
    const float* A_log  = (const float*)d_in[8];
    const float* D_ssm  = (const float*)d_in[9];
    const float* W_out  = (const float*)d_in[10];
    const float* ln2_w  = (const float*)d_in[11];
    const float* ln2_b  = (const float*)d_in[12];
    const float* W_f1   = (const float*)d_in[13];
    const float* W_f2   = (const float*)d_in[14];
    float* out = (float*)d_out;

    float* gb = nullptr;
    cudaGetSymbolAddress((void**)&gb, g_buf);

    prep_kernel<<<80, 256>>>(W_xp, W_dt);
    // GEMM1 + fused LN1: x[C,L] -> xi, z
    gemm_k<64, 256, 8, 8, 1, 256, 1><<<L / 64, 256>>>(x, W_in,
        gb + O_XI, gb + O_Z, nullptr, nullptr, ln1_w, ln1_b);
    conv_kernel<<<(L * 32) / 256, 256>>>(gb + O_XI, conv_w, gb + O_XC);
    // GEMM2: xc @ Wcomb -> delta (softplus fused), B, C
    gemm_k<128, 160, 8, 8, 2, 160, 0><<<L / 64, 160>>>(gb + O_XC, gb + O_WCOMB,
        gb + O_DELTA, gb + O_B, gb + O_C, dt_b, nullptr, nullptr);
    scan_a<<<NCH, 256>>>(gb + O_XC, gb + O_DELTA, gb + O_B, A_log);
    scan_b<<<2048, 256>>>();
    scan_c<<<NCH, 256>>>(gb + O_XC, gb + O_DELTA, gb + O_B, gb + O_C,
                         A_log, D_ssm, gb + O_Z, gb + O_YM);
    // GEMM3: ym @ W_out + x  -> res1 [L,64]
    gemm_k<128, 64, 8, 4, 3, 128, 0><<<L / 64, 128>>>(gb + O_YM, W_out,
        gb + O_RES1, nullptr, nullptr, x, nullptr, nullptr);
    // GEMM4 + fused LN2: LN(res1) @ W_f1 -> silu(g)*v
    gemm_k<64, 256, 8, 8, 4, 256, 2><<<L / 64, 256>>>(gb + O_RES1, W_f1,
        gb + O_HMID, nullptr, nullptr, nullptr, ln2_w, ln2_b);
    // GEMM5: hmid @ W_f2 + res1 -> out [C,L]
    gemm_k<128, 64, 8, 4, 5, 128, 0><<<L / 64, 128>>>(gb + O_HMID, W_f2,
        out, nullptr, nullptr, gb + O_RES1, nullptr, nullptr);
}

// round 13
// speedup vs baseline: 1.7214x; 1.6776x over previous
#include <cuda_runtime.h>
#include <cuda_bf16.h>
#include <stdint.h>
#include <math.h>

constexpr int L = 31744, NCH = 248, LC = 128;

// --------------------------- fp32 scratch ---------------------------------
constexpr size_t O_XI    = 0;
constexpr size_t O_Z     = O_XI    + (size_t)L * 128;
constexpr size_t O_XC    = O_Z     + (size_t)L * 128;
constexpr size_t O_DELTA = O_XC    + (size_t)L * 128;
constexpr size_t O_B     = O_DELTA + (size_t)L * 128;
constexpr size_t O_C     = O_B     + (size_t)L * 16;
constexpr size_t O_YM    = O_C     + (size_t)L * 16;
constexpr size_t O_RES1  = O_YM    + (size_t)L * 128;
constexpr size_t O_HMID  = O_RES1  + (size_t)L * 64;
constexpr size_t O_HLOC  = O_HMID  + (size_t)L * 128;
constexpr size_t O_P     = O_HLOC  + (size_t)NCH * 2048;
constexpr size_t O_HIN   = O_P     + (size_t)NCH * 2048;
constexpr size_t TOTALF  = O_HIN   + (size_t)NCH * 2048;
__device__ float g_buf[TOTALF];

// ---- bf16 weight images, transposed [N][K], rows padded to K+8 elems -----
constexpr int IMG_WIN   = 0;                          // N=256 K=64  stride 72
constexpr int IMG_WCOMB = IMG_WIN   + 256 * 72;       // N=160 K=128 stride 136
constexpr int IMG_WOUT  = IMG_WCOMB + 160 * 136;      // N=64  K=128 stride 136
constexpr int IMG_WF1   = IMG_WOUT  + 64 * 136;       // N=256 K=64  stride 72
constexpr int IMG_WF2   = IMG_WF1   + 256 * 72;       // N=64  K=128 stride 136
constexpr int IMG_TOTAL = IMG_WF2   + 64 * 136;
__device__ __align__(16) __nv_bfloat16 g_wimg[IMG_TOTAL];

__device__ __forceinline__ float softplusf(float x) {
    return (x > 20.f) ? x : log1pf(__expf(x));
}

__device__ __forceinline__ void mma16816(float* c, const uint32_t* a, const uint32_t* b) {
    asm volatile(
        "mma.sync.aligned.m16n8k16.row.col.f32.bf16.bf16.f32 "
        "{%0,%1,%2,%3}, {%4,%5,%6,%7}, {%8,%9}, {%0,%1,%2,%3};"
        : "+f"(c[0]), "+f"(c[1]), "+f"(c[2]), "+f"(c[3])
        : "r"(a[0]), "r"(a[1]), "r"(a[2]), "r"(a[3]), "r"(b[0]), "r"(b[1]));
}

// ------------------------------ prep ---------------------------------------
// builds transposed padded bf16 images; folds W_dt into Wcomb.
__global__ void prep_img(const float* __restrict__ Win, const float* __restrict__ Wxp,
                         const float* __restrict__ Wdt, const float* __restrict__ Wout,
                         const float* __restrict__ Wf1, const float* __restrict__ Wf2) {
    int idx = blockIdx.x * 256 + threadIdx.x;
    if (idx < 16384) {                                  // WIN: 256x64
        int n = idx / 64, k = idx % 64;
        g_wimg[IMG_WIN + n * 72 + k] = __float2bfloat16(Win[k * 256 + n]);
    } else if (idx < 16384 + 20480) {                   // WCOMB: 160x128
        int j = idx - 16384;
        int n = j / 128, k = j % 128;
        float v;
        if (n < 128) {
            v = 0.f;
            #pragma unroll
            for (int r = 0; r < 4; r++) v = fmaf(Wxp[k * 36 + r], Wdt[r * 128 + n], v);
        } else if (n < 144) v = Wxp[k * 36 + 4 + (n - 128)];
        else                v = Wxp[k * 36 + 20 + (n - 144)];
        g_wimg[IMG_WCOMB + n * 136 + k] = __float2bfloat16(v);
    } else if (idx < 36864 + 8192) {                    // WOUT: 64x128
        int j = idx - 36864;
        int n = j / 128, k = j % 128;
        g_wimg[IMG_WOUT + n * 136 + k] = __float2bfloat16(Wout[k * 64 + n]);
    } else if (idx < 45056 + 16384) {                   // WF1: 256x64
        int j = idx - 45056;
        int n = j / 64, k = j % 64;
        g_wimg[IMG_WF1 + n * 72 + k] = __float2bfloat16(Wf1[k * 256 + n]);
    } else if (idx < 61440 + 8192) {                    // WF2: 64x128
        int j = idx - 61440;
        int n = j / 128, k = j % 128;
        g_wimg[IMG_WF2 + n * 136 + k] = __float2bfloat16(Wf2[k * 64 + n]);
    }
}

// ------------------------- depthwise conv ----------------------------------
__global__ void __launch_bounds__(256) conv_kernel(const float* __restrict__ xi,
                                                   const float* __restrict__ cw,
                                                   float* __restrict__ xc) {
    int idx = blockIdx.x * 256 + threadIdx.x;
    int q = idx & 31, l = idx >> 5;
    int d0 = q * 4;
    const float4* xr = (const float4*)xi;
    float4 zero = make_float4(0.f, 0.f, 0.f, 0.f);
    float4 x0 = xr[(size_t)l * 32 + q];
    float4 x1 = (l > 0) ? xr[(size_t)(l - 1) * 32 + q] : zero;
    float4 x2 = (l > 1) ? xr[(size_t)(l - 2) * 32 + q] : zero;
    float4 x3 = (l > 2) ? xr[(size_t)(l - 3) * 32 + q] : zero;
    float4 w0 = *(const float4*)&cw[(d0 + 0) * 4];
    float4 w1 = *(const float4*)&cw[(d0 + 1) * 4];
    float4 w2 = *(const float4*)&cw[(d0 + 2) * 4];
    float4 w3 = *(const float4*)&cw[(d0 + 3) * 4];
    float4 o;
    o.x = fmaxf(fmaf(w0.w, x0.x, fmaf(w0.z, x1.x, fmaf(w0.y, x2.x, w0.x * x3.x))), 0.f);
    o.y = fmaxf(fmaf(w1.w, x0.y, fmaf(w1.z, x1.y, fmaf(w1.y, x2.y, w1.x * x3.y))), 0.f);
    o.z = fmaxf(fmaf(w2.w, x0.z, fmaf(w2.z, x1.z, fmaf(w2.y, x2.z, w2.x * x3.z))), 0.f);
    o.w = fmaxf(fmaf(w3.w, x0.w, fmaf(w3.z, x1.w, fmaf(w3.y, x2.w, w3.x * x3.w))), 0.f);
    ((float4*)xc)[(size_t)l * 32 + q] = o;
}

// ------------------- HMMA GEMM, 128-token tiles, 8 warps -------------------
// warp grid 4(M) x 2(N): warp handles 32 rows x (N/2) cols, n-tiles by parity.
// MODE 1: cols<128 -> O0 xi, cols>=128 -> O1 z (both [L,128])
// MODE 2: cols<128 -> O0 delta=softplus(v+E0[col]); 128..143 -> O1 B; 144..159 -> O2 C
// MODE 3: O0[l*64+c] = v + E0[c*L+l]
// MODE 4: O0[l*128+c] = silu(g)*v with g=col c, v=col c+128
// MODE 5: O0[c*L+l]  = E0[l*64+c] + v
// LNSRC 0: A = X [L,K] fp32. 1: X = x [C,L], fused LN. 2: X [L,64], fused LN.
template <int K, int N, int MODE, int LNSRC>
__global__ void __launch_bounds__(256) mma_gemm(
        const float* __restrict__ X, const __nv_bfloat16* __restrict__ Wt,
        float* __restrict__ O0, float* __restrict__ O1, float* __restrict__ O2,
        const float* __restrict__ E0, const float* __restrict__ lnw,
        const float* __restrict__ lnb) {
    constexpr int SA  = K + 8;           // padded stride (conflict-free frags)
    constexpr int NTW = N / 16;          // n-tiles per warp
    extern __shared__ char smem[];
    __nv_bfloat16* As = (__nv_bfloat16*)smem;                     // 128*SA
    __nv_bfloat16* Bs = (__nv_bfloat16*)(smem + 128 * SA * 2);    // N*SA
    float* Xf = (float*)(smem + 128 * SA * 2 + N * SA * 2);       // LNSRC==2

    const int tid = threadIdx.x;
    const int l0  = blockIdx.x * 128;

    // ---- stage B: raw copy of padded transposed image ----
    {
        const float4* src = (const float4*)Wt;
        float4* dst = (float4*)Bs;
        constexpr int n16 = N * SA * 2 / 16;
        for (int i = tid; i < n16; i += 256) dst[i] = src[i];
    }
    // ---- stage A (+ optional fused LN) ----
    if (LNSRC == 0) {
        for (int i = tid; i < 128 * (K / 4); i += 256) {
            int t = i / (K / 4), kq = i % (K / 4);
            float4 v = *(const float4*)&X[(size_t)(l0 + t) * K + kq * 4];
            __nv_bfloat162* dst = (__nv_bfloat162*)&As[t * SA + kq * 4];
            dst[0] = __floats2bfloat162_rn(v.x, v.y);
            dst[1] = __floats2bfloat162_rn(v.z, v.w);
        }
    } else if (LNSRC == 1) {             // x [C,L], K==64
        if (tid < 128) {
            int t = tid;
            float v[64], mu = 0.f, sq = 0.f;
            #pragma unroll
            for (int c = 0; c < 64; c++) {
                v[c] = X[(size_t)c * L + l0 + t];
                mu += v[c]; sq = fmaf(v[c], v[c], sq);
            }
            mu *= (1.f / 64.f);
            float rs = rsqrtf(sq * (1.f / 64.f) - mu * mu + 1e-5f);
            #pragma unroll
            for (int c = 0; c < 64; c += 2) {
                float a = (v[c] - mu) * rs * lnw[c] + lnb[c];
                float b = (v[c + 1] - mu) * rs * lnw[c + 1] + lnb[c + 1];
                *(__nv_bfloat162*)&As[t * SA + c] = __floats2bfloat162_rn(a, b);
            }
        }
    } else {                             // X [L,64] row-major, K==64
        for (int i = tid; i < 128 * 16; i += 256) {
            int t = i >> 4, q = i & 15;
            *(float4*)&Xf[t * 68 + q * 4] =
                *(const float4*)&X[(size_t)(l0 + t) * 64 + q * 4];
        }
        __syncthreads();
        if (tid < 128) {
            int t = tid;
            float v[64], mu = 0.f, sq = 0.f;
            #pragma unroll
            for (int c = 0; c < 64; c++) {
                v[c] = Xf[t * 68 + c];
                mu += v[c]; sq = fmaf(v[c], v[c], sq);
            }
            mu *= (1.f / 64.f);
            float rs = rsqrtf(sq * (1.f / 64.f) - mu * mu + 1e-5f);
            #pragma unroll
            for (int c = 0; c < 64; c += 2) {
                float a = (v[c] - mu) * rs * lnw[c] + lnb[c];
                float b = (v[c + 1] - mu) * rs * lnw[c + 1] + lnb[c + 1];
                *(__nv_bfloat162*)&As[t * SA + c] = __floats2bfloat162_rn(a, b);
            }
        }
    }
    __syncthreads();

    // ---- compute ----
    const int lane = tid & 31, wid = tid >> 5;
    const int wr = wid >> 1, wc = wid & 1;
    const int g = lane >> 2, tg = lane & 3;
    const int m0 = wr * 32;

    float acc[2][NTW][4];
    #pragma unroll
    for (int mt = 0; mt < 2; mt++)
        #pragma unroll
        for (int i = 0; i < NTW; i++)
            #pragma unroll
            for (int q = 0; q < 4; q++) acc[mt][i][q] = 0.f;

    #pragma unroll
    for (int ks = 0; ks < K / 16; ks++) {
        const int kb = ks * 16 + tg * 2;
        uint32_t a[2][4];
        #pragma unroll
        for (int mt = 0; mt < 2; mt++) {
            int r = m0 + mt * 16 + g;
            a[mt][0] = *(const uint32_t*)&As[r * SA + kb];
            a[mt][1] = *(const uint32_t*)&As[(r + 8) * SA + kb];
            a[mt][2] = *(const uint32_t*)&As[r * SA + kb + 8];
            a[mt][3] = *(const uint32_t*)&As[(r + 8) * SA + kb + 8];
        }
        #pragma unroll
        for (int i = 0; i < NTW; i++) {
            int n = (wc + 2 * i) * 8 + g;
            uint32_t b[2];
            b[0] = *(const uint32_t*)&Bs[n * SA + kb];
            b[1] = *(const uint32_t*)&Bs[n * SA + kb + 8];
            mma16816(acc[0][i], a[0], b);
            mma16816(acc[1][i], a[1], b);
        }
    }

    // ---- epilogue ----
    #pragma unroll
    for (int mt = 0; mt < 2; mt++) {
        #pragma unroll
        for (int i = 0; i < (MODE == 4 ? NTW / 2 : NTW); i++) {
            const int col = (wc + 2 * i) * 8 + tg * 2;
            #pragma unroll
            for (int h = 0; h < 2; h++) {
                const int l = l0 + m0 + mt * 16 + g + h * 8;
                float v0 = acc[mt][i][h * 2 + 0];
                float v1 = acc[mt][i][h * 2 + 1];
                if (MODE == 1) {
                    float* dst = (col < 128) ? (O0 + (size_t)l * 128 + col)
                                             : (O1 + (size_t)l * 128 + col - 128);
                    *(float2*)dst = make_float2(v0, v1);
                } else if (MODE == 2) {
                    if (col < 128) {
                        float2 o = make_float2(softplusf(v0 + E0[col]),
                                               softplusf(v1 + E0[col + 1]));
                        *(float2*)(O0 + (size_t)l * 128 + col) = o;
                    } else if (col < 144) {
                        *(float2*)(O1 + (size_t)l * 16 + col - 128) = make_float2(v0, v1);
                    } else {
                        *(float2*)(O2 + (size_t)l * 16 + col - 144) = make_float2(v0, v1);
                    }
                } else if (MODE == 3) {
                    O0[(size_t)l * 64 + col]     = v0 + E0[(size_t)col * L + l];
                    O0[(size_t)l * 64 + col + 1] = v1 + E0[(size_t)(col + 1) * L + l];
                } else if (MODE == 4) {
                    float w0 = acc[mt][i + NTW / 2][h * 2 + 0];
                    float w1 = acc[mt][i + NTW / 2][h * 2 + 1];
                    float o0 = v0 * w0 / (1.f + __expf(-v0));
                    float o1 = v1 * w1 / (1.f + __expf(-v1));
                    *(float2*)(O0 + (size_t)l * 128 + col) = make_float2(o0, o1);
                } else {  // MODE 5
                    O0[(size_t)col * L + l]       = E0[(size_t)l * 64 + col] + v0;
                    O0[(size_t)(col + 1) * L + l] = E0[(size_t)l * 64 + col + 1] + v1;
                }
            }
        }
    }
}

// ------------------------- selective scan (3 phases) -----------------------
__global__ void __launch_bounds__(256) scan_a(const float* __restrict__ u,
                                              const float* __restrict__ dl,
                                              const float* __restrict__ Bm,
                                              const float* __restrict__ Alog) {
    __shared__ float Bs[LC * 16];
    const int tid = threadIdx.x, chunk = blockIdx.x, l0 = chunk * LC;
    for (int i = tid; i < LC * 16; i += 256) Bs[i] = Bm[(size_t)l0 * 16 + i];
    __syncthreads();
    const int d = tid >> 1, s0 = (tid & 1) * 8;
    float A[8], h[8], sd = 0.f;
    #pragma unroll
    for (int j = 0; j < 8; j++) { A[j] = -__expf(Alog[d * 16 + s0 + j]); h[j] = 0.f; }
    for (int l = 0; l < LC; l++) {
        float del = dl[(size_t)(l0 + l) * 128 + d];
        float du  = del * u[(size_t)(l0 + l) * 128 + d];
        sd += del;
        #pragma unroll
        for (int j = 0; j < 8; j++)
            h[j] = __expf(del * A[j]) * h[j] + du * Bs[l * 16 + s0 + j];
    }
    size_t base = (size_t)chunk * 2048 + d * 16 + s0;
    #pragma unroll
    for (int j = 0; j < 8; j++) {
        g_buf[O_HLOC + base + j] = h[j];
        g_buf[O_P + base + j]    = __expf(sd * A[j]);
    }
}

__global__ void __launch_bounds__(256) scan_b() {
    __shared__ float a0[256], b0[256], a1[256], b1[256];
    const int lane = blockIdx.x;
    const int c = threadIdx.x;
    float a = 1.f, b = 0.f;
    if (c < NCH) {
        a = g_buf[O_P + (size_t)c * 2048 + lane];
        b = g_buf[O_HLOC + (size_t)c * 2048 + lane];
    }
    a0[c] = a; b0[c] = b;
    __syncthreads();
    bool pp = true;
    #pragma unroll
    for (int d = 1; d < 256; d <<= 1) {
        float na = a, nb = b;
        if (c >= d) {
            float la = pp ? a0[c - d] : a1[c - d];
            float lb = pp ? b0[c - d] : b1[c - d];
            na = la * a;
            nb = a * lb + b;
        }
        __syncthreads();
        a = na; b = nb;
        if (pp) { a1[c] = a; b1[c] = b; } else { a0[c] = a; b0[c] = b; }
        pp = !pp;
        __syncthreads();
    }
    if (c < NCH) {
        float hin = (c == 0) ? 0.f : (pp ? b0[c - 1] : b1[c - 1]);
        g_buf[O_HIN + (size_t)c * 2048 + lane] = hin;
    }
}

__global__ void __launch_bounds__(256) scan_c(const float* __restrict__ u,
                                              const float* __restrict__ dl,
                                              const float* __restrict__ Bm,
                                              const float* __restrict__ Cm,
                                              const float* __restrict__ Alog,
                                              const float* __restrict__ Dp,
                                              const float* __restrict__ z,
                                              float* __restrict__ ym) {
    __shared__ float Bs[LC * 16], Cs[LC * 16];
    const int tid = threadIdx.x, chunk = blockIdx.x, l0 = chunk * LC;
    for (int i = tid; i < LC * 16; i += 256) {
        Bs[i] = Bm[(size_t)l0 * 16 + i];
        Cs[i] = Cm[(size_t)l0 * 16 + i];
    }
    __syncthreads();
    const int d = tid >> 1, s0 = (tid & 1) * 8;
    float A[8], h[8];
    const float Dd = Dp[d];
    size_t base = (size_t)chunk * 2048 + d * 16 + s0;
    #pragma unroll
    for (int j = 0; j < 8; j++) {
        A[j] = -__expf(Alog[d * 16 + s0 + j]);
        h[j] = g_buf[O_HIN + base + j];
    }
    for (int l = 0; l < LC; l++) {
        float del = dl[(size_t)(l0 + l) * 128 + d];
        float ul  = u[(size_t)(l0 + l) * 128 + d];
        float du  = del * ul;
        float part = 0.f;
        #pragma unroll
        for (int j = 0; j < 8; j++) {
            h[j] = __expf(del * A[j]) * h[j] + du * Bs[l * 16 + s0 + j];
            part = fmaf(h[j], Cs[l * 16 + s0 + j], part);
        }
        float other = __shfl_xor_sync(0xffffffffu, part, 1);
        float y = part + other + ul * Dd;
        if ((tid & 1) == 0) {
            float zz = z[(size_t)(l0 + l) * 128 + d];
            ym[(size_t)(l0 + l) * 128 + d] = y * zz / (1.f + __expf(-zz));
        }
    }
}

// ---------------------------------------------------------------------------
extern "C" void kernel_launch(void* const* d_in, const int* in_sizes, int n_in,
                              void* d_out, int out_size) {
    const float* x      = (const float*)d_in[0];
    const float* ln1_w  = (const float*)d_in[1];
    const float* ln1_b  = (const float*)d_in[2];
    const float* W_in   = (const float*)d_in[3];
    const float* conv_w = (const float*)d_in[4];
    const float* W_xp   = (const float*)d_in[5];
    const float* W_dt   = (const float*)d_in[6];
    const float* dt_b   = (const float*)d_in[7];
    const float* A_log  = (const float*)d_in[8];
    const float* D_ssm  = (const float*)d_in[9];
    const float* W_out  = (const float*)d_in[10];
    const float* ln2_w  = (const float*)d_in[11];
    const float* ln2_b  = (const float*)d_in[12];
    const float* W_f1   = (const float*)d_in[13];
    const float* W_f2   = (const float*)d_in[14];
    float* out = (float*)d_out;

    float* gb = nullptr;
    cudaGetSymbolAddress((void**)&gb, g_buf);
    __nv_bfloat16* wi = nullptr;
    cudaGetSymbolAddress((void**)&wi, g_wimg);

    // smem: A(128*SA*2) + B(N*SA*2) [+ Xf for LNSRC==2]
    constexpr int S1 = 128 * 72 * 2 + 256 * 72 * 2;                   // 55296
    constexpr int S2 = 128 * 136 * 2 + 160 * 136 * 2;                 // 78336
    constexpr int S3 = 128 * 136 * 2 + 64 * 136 * 2;                  // 52224
    constexpr int S4 = 128 * 72 * 2 + 256 * 72 * 2 + 128 * 68 * 4;    // 90112
    constexpr int S5 = S3;
    cudaFuncSetAttribute(mma_gemm<64, 256, 1, 1>, cudaFuncAttributeMaxDynamicSharedMemorySize, S1);
    cudaFuncSetAttribute(mma_gemm<128, 160, 2, 0>, cudaFuncAttributeMaxDynamicSharedMemorySize, S2);
    cudaFuncSetAttribute(mma_gemm<128, 64, 3, 0>, cudaFuncAttributeMaxDynamicSharedMemorySize, S3);
    cudaFuncSetAttribute(mma_gemm<64, 256, 4, 2>, cudaFuncAttributeMaxDynamicSharedMemorySize, S4);
    cudaFuncSetAttribute(mma_gemm<128, 64, 5, 0>, cudaFuncAttributeMaxDynamicSharedMemorySize, S5);

    prep_img<<<(69632 + 255) / 256, 256>>>(W_in, W_xp, W_dt, W_out, W_f1, W_f2);

    // GEMM1 + LN1: x[C,L] -> xi,z
    mma_gemm<64, 256, 1, 1><<<NCH, 256, S1>>>(x, wi + IMG_WIN,
        gb + O_XI, gb + O_Z, nullptr, nullptr, ln1_w, ln1_b);
    conv_kernel<<<(L * 32) / 256, 256>>>(gb + O_XI, conv_w, gb + O_XC);
    // GEMM2: xc @ Wcomb -> delta(softplus), B, C
    mma_gemm<128, 160, 2, 0><<<NCH, 256, S2>>>(gb + O_XC, wi + IMG_WCOMB,
        gb + O_DELTA, gb + O_B, gb + O_C, dt_b, nullptr, nullptr);
    scan_a<<<NCH, 256>>>(gb + O_XC, gb + O_DELTA, gb + O_B, A_log);
    scan_b<<<2048, 256>>>();
    scan_c<<<NCH, 256>>>(gb + O_XC, gb + O_DELTA, gb + O_B, gb + O_C,
                         A_log, D_ssm, gb + O_Z, gb + O_YM);
    // GEMM3: ym @ W_out + x -> res1 [L,64]
    mma_gemm<128, 64, 3, 0><<<NCH, 256, S3>>>(gb + O_YM, wi + IMG_WOUT,
        gb + O_RES1, nullptr, nullptr, x, nullptr, nullptr);
    // GEMM4 + LN2: LN(res1) @ W_f1 -> silu(g)*v
    mma_gemm<64, 256, 4, 2><<<NCH, 256, S4>>>(gb + O_RES1, wi + IMG_WF1,
        gb + O_HMID, nullptr, nullptr, nullptr, ln2_w, ln2_b);
    // GEMM5: hmid @ W_f2 + res1 -> out [C,L]
    mma_gemm<128, 64, 5, 0><<<NCH, 256, S5>>>(gb + O_HMID, wi + IMG_WF2,
        out, nullptr, nullptr, gb + O_RES1, nullptr, nullptr);
}